// round 11
// baseline (speedup 1.0000x reference)
#include <cuda_runtime.h>
#include <cuda_bf16.h>
#include <cstdint>

#define NEXP     16
#define DIM      256     // K
#define PP       64      // N
#define TCHUNK   4096
#define MT       64      // M tile rows
#define NTHREADS 512

// smem (bytes): A buffers 2 x (hi 32KB + lo 32KB), B hi/lo, rows
#define SM_A(b)  ((b) * 65536)          // AH at +0, AL at +32768
#define SM_BH    131072
#define SM_BL    163840
#define SM_ROWS  196608                 // 4096 ints = 16KB
#define SMEM_DYN 212992                 // 208 KB

// prepped weights: [E][N][K] bf16, hi = truncated top-16, lo = rounded residual
__device__ __nv_bfloat16 g_Wh[NEXP * PP * DIM];
__device__ __nv_bfloat16 g_Wl[NEXP * PP * DIM];

__device__ __forceinline__ uint32_t smem_u32(const void* p) {
    uint32_t a;
    asm("{ .reg .u64 t; cvta.to.shared.u64 t, %1; cvt.u32.u64 %0, t; }" : "=r"(a) : "l"(p));
    return a;
}

// Swizzled tile: row-major [r][k] bf16, row stride 512B; 16B chunks XOR-permuted
// within each 128B group -> ldmatrix (8 rows, same k-chunk) conflict-free.
__device__ __forceinline__ uint32_t tile_off(uint32_t r, uint32_t k) {
    uint32_t ch  = k >> 3;
    uint32_t chs = (ch & 24u) | ((ch ^ r) & 7u);
    return r * 512u + chs * 16u + (k & 7u) * 2u;
}

__device__ __forceinline__ void ldmx4(uint32_t (&r)[4], uint32_t a) {
    asm volatile("ldmatrix.sync.aligned.m8n8.x4.shared.b16 {%0,%1,%2,%3}, [%4];"
                 : "=r"(r[0]), "=r"(r[1]), "=r"(r[2]), "=r"(r[3]) : "r"(a));
}

__device__ __forceinline__ void mma16816(float (&d)[4], const uint32_t (&a)[4],
                                         uint32_t b0, uint32_t b1) {
    asm volatile("mma.sync.aligned.m16n8k16.row.col.f32.bf16.bf16.f32 "
                 "{%0,%1,%2,%3}, {%4,%5,%6,%7}, {%8,%9}, {%0,%1,%2,%3};"
                 : "+f"(d[0]), "+f"(d[1]), "+f"(d[2]), "+f"(d[3])
                 : "r"(a[0]), "r"(a[1]), "r"(a[2]), "r"(a[3]), "r"(b0), "r"(b1));
}

__device__ __forceinline__ uint32_t bf16x2(float hi_e, float lo_e) {
    uint32_t r;
    asm("cvt.rn.bf16x2.f32 %0, %1, %2;" : "=r"(r) : "f"(hi_e), "f"(lo_e));
    return r;
}

// split 8 consecutive f32 -> hi (truncated bf16) + lo (rounded residual bf16)
__device__ __forceinline__ void split8(const float4 v0, const float4 v1,
                                       uint4& hi, uint4& lo) {
    uint32_t u0=__float_as_uint(v0.x), u1=__float_as_uint(v0.y);
    uint32_t u2=__float_as_uint(v0.z), u3=__float_as_uint(v0.w);
    uint32_t u4=__float_as_uint(v1.x), u5=__float_as_uint(v1.y);
    uint32_t u6=__float_as_uint(v1.z), u7=__float_as_uint(v1.w);
    hi.x=(u0>>16)|(u1&0xFFFF0000u); hi.y=(u2>>16)|(u3&0xFFFF0000u);
    hi.z=(u4>>16)|(u5&0xFFFF0000u); hi.w=(u6>>16)|(u7&0xFFFF0000u);
    lo.x=bf16x2(v0.y-__uint_as_float(u1&0xFFFF0000u), v0.x-__uint_as_float(u0&0xFFFF0000u));
    lo.y=bf16x2(v0.w-__uint_as_float(u3&0xFFFF0000u), v0.z-__uint_as_float(u2&0xFFFF0000u));
    lo.z=bf16x2(v1.y-__uint_as_float(u5&0xFFFF0000u), v1.x-__uint_as_float(u4&0xFFFF0000u));
    lo.w=bf16x2(v1.w-__uint_as_float(u7&0xFFFF0000u), v1.z-__uint_as_float(u6&0xFFFF0000u));
}

// ---- prep: W [E][K][N] f32 -> g_Wh/g_Wl [E][N][K] bf16 (smem-tiled transpose) ----
__global__ void prep_W(const float* __restrict__ W) {
    __shared__ float tile[64][65];
    const int b  = blockIdx.x;          // 64 blocks: e (16) x k-seg (4)
    const int e  = b >> 2;
    const int k0 = (b & 3) * 64;
    const int t  = threadIdx.x;
    #pragma unroll
    for (int i = 0; i < 16; i++) {
        int idx = i * 256 + t;
        int kk = idx >> 6, nn = idx & 63;
        tile[kk][nn] = W[((size_t)e * DIM + k0 + kk) * PP + nn];
    }
    __syncthreads();
    #pragma unroll
    for (int i = 0; i < 16; i++) {
        int idx = i * 256 + t;
        int nn = idx >> 6, kk = idx & 63;
        float w = tile[kk][nn];
        uint32_t u = __float_as_uint(w);
        float hif = __uint_as_float(u & 0xFFFF0000u);
        size_t o = ((size_t)e * PP + nn) * DIM + k0 + kk;
        g_Wh[o] = __ushort_as_bfloat16((unsigned short)(u >> 16));
        g_Wl[o] = __float2bfloat16(w - hif);
    }
}

extern __shared__ char smem_raw[];

__global__ __launch_bounds__(NTHREADS, 1)
void moe_mma_kernel(const float* __restrict__ x,
                    const float* __restrict__ bias,
                    const int*   __restrict__ bidx,
                    float*       __restrict__ out,
                    int n_tokens)
{
    __shared__ int s_cnt;
    char* smem = smem_raw;
    const uint32_t sb = smem_u32(smem);
    int* s_rows = (int*)(smem + SM_ROWS);

    const int tid  = threadIdx.x;
    const int wid  = tid >> 5;
    const int lane = tid & 31;
    const int e    = blockIdx.y;
    const int base = blockIdx.x * TCHUNK;

    if (tid == 0) s_cnt = 0;
    __syncthreads();

    // ---- stage B = W[e] hi/lo into swizzled smem ----
    {
        const __nv_bfloat16* wh = g_Wh + (size_t)e * PP * DIM;
        const __nv_bfloat16* wl = g_Wl + (size_t)e * PP * DIM;
        #pragma unroll
        for (int p = 0; p < (PP * DIM / 8) / NTHREADS; p++) {   // 4 passes
            int i  = p * NTHREADS + tid;
            int n  = i >> 5;
            int k8 = (i & 31) * 8;
            uint32_t so = tile_off((uint32_t)n, (uint32_t)k8);
            *(uint4*)(smem + SM_BH + so) = *(const uint4*)(wh + (size_t)n * DIM + k8);
            *(uint4*)(smem + SM_BL + so) = *(const uint4*)(wl + (size_t)n * DIM + k8);
        }
    }

    // ---- select tokens for expert e ----
    int lim = n_tokens - base;
    if (lim > TCHUNK) lim = TCHUNK;
    for (int i = tid; i < lim; i += NTHREADS) {
        if (bidx[base + i] == e) {
            int pos = atomicAdd(&s_cnt, 1);
            s_rows[pos] = base + i;
        }
    }
    __syncthreads();
    const int cnt = s_cnt;
    if (cnt == 0) return;

    // warp geometry: 2m x 4n x 2k (16 warps), warp tile 32m x 16n, k-half 128
    const int kw    = wid & 1;
    const int wn    = (wid >> 1) & 3;
    const int wm    = wid >> 3;
    const int m_base = wm * 32;
    const int n_base = wn * 16;
    const int kbase  = kw * 128;

    const uint32_t rgrp = (uint32_t)((lane & 7) + ((lane >> 3) & 1) * 8);
    const uint32_t kofs = (uint32_t)((lane >> 4) * 8);
    const uint32_t rowA = (uint32_t)m_base + rgrp;
    const uint32_t rowB = (uint32_t)n_base + rgrp;

    float2 bc[2];
    #pragma unroll
    for (int nj = 0; nj < 2; nj++)
        bc[nj] = *(const float2*)(bias + e * PP + n_base + nj * 8 + (lane & 3) * 2);

    // staging map: 8 threads per row, 32 floats each
    const int st_r  = tid >> 3;
    const int st_ks = (tid & 7) * 32;

    const int ntiles = (cnt + MT - 1) >> 6;

    // ---- prologue: stage tile 0 into buffer 0 ----
    {
        int ri = st_r < cnt ? st_r : cnt - 1;
        const float* xr = x + (size_t)s_rows[ri] * DIM + st_ks;
        #pragma unroll
        for (int c = 0; c < 4; c++) {
            int kb = c * 8;
            float4 v0 = *(const float4*)(xr + kb);
            float4 v1 = *(const float4*)(xr + kb + 4);
            uint4 hi, lo;
            split8(v0, v1, hi, lo);
            uint32_t so = tile_off((uint32_t)st_r, (uint32_t)(st_ks + kb));
            *(uint4*)(smem + SM_A(0) + so) = hi;
            *(uint4*)(smem + SM_A(0) + 32768 + so) = lo;
        }
    }
    __syncthreads();

    float4 pf[4];   // prefetch of floats [st_ks, st_ks+16) of next tile's row

    for (int t = 0; t < ntiles; t++) {
        const int  cb = t & 1, nb = cb ^ 1;
        const bool hn = (t + 1) < ntiles;
        const float* xrn = nullptr;
        if (hn) {
            int ri = (t + 1) * MT + st_r;
            if (ri >= cnt) ri = cnt - 1;
            xrn = x + (size_t)s_rows[ri] * DIM + st_ks;
            #pragma unroll
            for (int j = 0; j < 4; j++) pf[j] = *(const float4*)(xrn + j * 4);
        }

        // ---- compute (all 16 warps, k-half each) ----
        float acc[2][2][4];
        #pragma unroll
        for (int i = 0; i < 2; i++)
            #pragma unroll
            for (int j = 0; j < 2; j++)
                #pragma unroll
                for (int q = 0; q < 4; q++) acc[i][j][q] = 0.f;

        const uint32_t abase = sb + SM_A(cb);
        #pragma unroll
        for (int ks = 0; ks < 8; ks++) {
            const uint32_t kk = (uint32_t)(kbase + ks * 16) + kofs;
            uint32_t aoff = tile_off(rowA, kk);
            uint32_t boff = tile_off(rowB, kk);

            uint32_t AH0[4], AH1[4], AL0[4], AL1[4], BH[4], BL[4];
            ldmx4(AH0, abase + aoff);
            ldmx4(BH,  sb + SM_BH + boff);
            ldmx4(AH1, abase + aoff + 16 * 512);
            ldmx4(BL,  sb + SM_BL + boff);
            ldmx4(AL0, abase + 32768 + aoff);
            ldmx4(AL1, abase + 32768 + aoff + 16 * 512);

            mma16816(acc[0][0], AH0, BH[0], BH[2]);
            mma16816(acc[0][1], AH0, BH[1], BH[3]);
            mma16816(acc[1][0], AH1, BH[0], BH[2]);
            mma16816(acc[1][1], AH1, BH[1], BH[3]);
            mma16816(acc[0][0], AL0, BH[0], BH[2]);
            mma16816(acc[0][1], AL0, BH[1], BH[3]);
            mma16816(acc[1][0], AL1, BH[0], BH[2]);
            mma16816(acc[1][1], AL1, BH[1], BH[3]);
            mma16816(acc[0][0], AH0, BL[0], BL[2]);
            mma16816(acc[0][1], AH0, BL[1], BL[3]);
            mma16816(acc[1][0], AH1, BL[0], BL[2]);
            mma16816(acc[1][1], AH1, BL[1], BL[3]);
        }
        __syncthreads();

        // ---- k-reduction via free A buffer (first 16KB of buf nb) ----
        const uint32_t red = sb + SM_A(nb) + (uint32_t)(wm * 4 + wn) * 2048
                           + (uint32_t)lane * 16;
        if (kw) {
            #pragma unroll
            for (int mi = 0; mi < 2; mi++)
                #pragma unroll
                for (int nj = 0; nj < 2; nj++)
                    *(float4*)((char*)smem + (red - sb) + (mi * 2 + nj) * 512) =
                        *(float4*)acc[mi][nj];
        }
        __syncthreads();
        if (!kw) {
            int mcount = cnt - t * MT;
            if (mcount > MT) mcount = MT;
            #pragma unroll
            for (int mi = 0; mi < 2; mi++) {
                int r0 = m_base + mi * 16 + (lane >> 2);
                int r1 = r0 + 8;
                #pragma unroll
                for (int nj = 0; nj < 2; nj++) {
                    float4 o = *(float4*)((char*)smem + (red - sb) + (mi * 2 + nj) * 512);
                    if (r0 < mcount) {
                        float2 v = make_float2(acc[mi][nj][0] + o.x + bc[nj].x,
                                               acc[mi][nj][1] + o.y + bc[nj].y);
                        *(float2*)(out + (size_t)s_rows[t * MT + r0] * PP
                                   + n_base + nj * 8 + (lane & 3) * 2) = v;
                    }
                    if (r1 < mcount) {
                        float2 v = make_float2(acc[mi][nj][2] + o.z + bc[nj].x,
                                               acc[mi][nj][3] + o.w + bc[nj].y);
                        *(float2*)(out + (size_t)s_rows[t * MT + r1] * PP
                                   + n_base + nj * 8 + (lane & 3) * 2) = v;
                    }
                }
            }
        }
        __syncthreads();

        // ---- stage tile t+1 into buf nb: prefetched half + live half ----
        if (hn) {
            #pragma unroll
            for (int c = 0; c < 2; c++) {      // floats [st_ks, st_ks+16)
                uint4 hi, lo;
                split8(pf[c * 2], pf[c * 2 + 1], hi, lo);
                uint32_t so = tile_off((uint32_t)st_r, (uint32_t)(st_ks + c * 8));
                *(uint4*)(smem + SM_A(nb) + so) = hi;
                *(uint4*)(smem + SM_A(nb) + 32768 + so) = lo;
            }
            #pragma unroll
            for (int c = 0; c < 2; c++) {      // floats [st_ks+16, st_ks+32)
                int kb = 16 + c * 8;
                float4 v0 = *(const float4*)(xrn + kb);
                float4 v1 = *(const float4*)(xrn + kb + 4);
                uint4 hi, lo;
                split8(v0, v1, hi, lo);
                uint32_t so = tile_off((uint32_t)st_r, (uint32_t)(st_ks + kb));
                *(uint4*)(smem + SM_A(nb) + so) = hi;
                *(uint4*)(smem + SM_A(nb) + 32768 + so) = lo;
            }
        }
        __syncthreads();
    }
}

extern "C" void kernel_launch(void* const* d_in, const int* in_sizes, int n_in,
                              void* d_out, int out_size) {
    const float* x    = (const float*)d_in[0];
    const float* W    = (const float*)d_in[1];
    const float* bias = (const float*)d_in[2];
    const int*   idx  = (const int*)d_in[3];
    float*       out  = (float*)d_out;

    const int n_tokens = in_sizes[3];

    prep_W<<<64, 256>>>(W);

    cudaFuncSetAttribute(moe_mma_kernel,
                         cudaFuncAttributeMaxDynamicSharedMemorySize, SMEM_DYN);

    dim3 grid((n_tokens + TCHUNK - 1) / TCHUNK, NEXP);
    moe_mma_kernel<<<grid, NTHREADS, SMEM_DYN>>>(x, bias, idx, out, n_tokens);
}

// round 12
// speedup vs baseline: 1.6348x; 1.6348x over previous
#include <cuda_runtime.h>
#include <cuda_fp16.h>
#include <cstdint>

#define NEXP     16
#define DIM      256     // K
#define PP       64      // N
#define TCHUNK   4096
#define MT       64      // M tile rows
#define NTHREADS 256

// smem (bytes): A [64][256] fp16 swizzled 32KB | B [64][256] fp16 swizzled 32KB | rows 16KB
#define SM_A     0
#define SM_B     32768
#define SM_ROWS  65536
#define SMEM_DYN 81920

// prepped weights: [E][N][K] fp16 (rounded)
__device__ __half g_Wt[NEXP * PP * DIM];

__device__ __forceinline__ uint32_t smem_u32(const void* p) {
    uint32_t a;
    asm("{ .reg .u64 t; cvta.to.shared.u64 t, %1; cvt.u32.u64 %0, t; }" : "=r"(a) : "l"(p));
    return a;
}

// Swizzled tile: row-major [r][k] fp16, row stride 512B; 16B chunks XOR-permuted
// within each 128B group -> ldmatrix (8 rows, same k-chunk) conflict-free.
__device__ __forceinline__ uint32_t tile_off(uint32_t r, uint32_t k) {
    uint32_t ch  = k >> 3;
    uint32_t chs = (ch & 24u) | ((ch ^ r) & 7u);
    return r * 512u + chs * 16u + (k & 7u) * 2u;
}

__device__ __forceinline__ void ldmx4(uint32_t (&r)[4], uint32_t a) {
    asm volatile("ldmatrix.sync.aligned.m8n8.x4.shared.b16 {%0,%1,%2,%3}, [%4];"
                 : "=r"(r[0]), "=r"(r[1]), "=r"(r[2]), "=r"(r[3]) : "r"(a));
}

__device__ __forceinline__ void mma16816(float (&d)[4], const uint32_t (&a)[4],
                                         uint32_t b0, uint32_t b1) {
    asm volatile("mma.sync.aligned.m16n8k16.row.col.f32.f16.f16.f32 "
                 "{%0,%1,%2,%3}, {%4,%5,%6,%7}, {%8,%9}, {%0,%1,%2,%3};"
                 : "+f"(d[0]), "+f"(d[1]), "+f"(d[2]), "+f"(d[3])
                 : "r"(a[0]), "r"(a[1]), "r"(a[2]), "r"(a[3]), "r"(b0), "r"(b1));
}

// pack two f32 -> f16x2, element e0 in low half
__device__ __forceinline__ uint32_t f16x2(float e1, float e0) {
    uint32_t r;
    asm("cvt.rn.f16x2.f32 %0, %1, %2;" : "=r"(r) : "f"(e1), "f"(e0));
    return r;
}

// convert 8 consecutive f32 -> 8 fp16 packed in uint4
__device__ __forceinline__ uint4 cvt8(const float4 v0, const float4 v1) {
    uint4 o;
    o.x = f16x2(v0.y, v0.x);
    o.y = f16x2(v0.w, v0.z);
    o.z = f16x2(v1.y, v1.x);
    o.w = f16x2(v1.w, v1.z);
    return o;
}

// ---- prep: W [E][K][N] f32 -> g_Wt [E][N][K] fp16 (smem-tiled transpose) ----
__global__ void prep_W(const float* __restrict__ W) {
    __shared__ float tile[64][65];
    const int b  = blockIdx.x;          // 64 blocks: e (16) x k-seg (4)
    const int e  = b >> 2;
    const int k0 = (b & 3) * 64;
    const int t  = threadIdx.x;
    #pragma unroll
    for (int i = 0; i < 16; i++) {
        int idx = i * 256 + t;
        int kk = idx >> 6, nn = idx & 63;
        tile[kk][nn] = W[((size_t)e * DIM + k0 + kk) * PP + nn];
    }
    __syncthreads();
    #pragma unroll
    for (int i = 0; i < 16; i++) {
        int idx = i * 256 + t;
        int nn = idx >> 6, kk = idx & 63;
        g_Wt[((size_t)e * PP + nn) * DIM + k0 + kk] = __float2half_rn(tile[kk][nn]);
    }
}

extern __shared__ char smem_raw[];

__global__ __launch_bounds__(NTHREADS, 2)
void moe_mma_kernel(const float* __restrict__ x,
                    const float* __restrict__ bias,
                    const int*   __restrict__ bidx,
                    float*       __restrict__ out,
                    int n_tokens)
{
    __shared__ int s_cnt;
    char* smem = smem_raw;
    const uint32_t sb = smem_u32(smem);
    int* s_rows = (int*)(smem + SM_ROWS);

    const int tid  = threadIdx.x;
    const int wid  = tid >> 5;
    const int lane = tid & 31;
    const int e    = blockIdx.y;
    const int base = blockIdx.x * TCHUNK;

    if (tid == 0) s_cnt = 0;
    __syncthreads();

    // ---- stage B = W[e] fp16 into swizzled smem ----
    {
        const __half* wt = g_Wt + (size_t)e * PP * DIM;
        #pragma unroll
        for (int p = 0; p < (PP * DIM / 8) / NTHREADS; p++) {   // 8 passes
            int i  = p * NTHREADS + tid;
            int n  = i >> 5;
            int k8 = (i & 31) * 8;
            uint32_t so = tile_off((uint32_t)n, (uint32_t)k8);
            *(uint4*)(smem + SM_B + so) = *(const uint4*)(wt + (size_t)n * DIM + k8);
        }
    }

    // ---- select tokens for expert e ----
    int lim = n_tokens - base;
    if (lim > TCHUNK) lim = TCHUNK;
    for (int i = tid; i < lim; i += NTHREADS) {
        if (bidx[base + i] == e) {
            int pos = atomicAdd(&s_cnt, 1);
            s_rows[pos] = base + i;
        }
    }
    __syncthreads();
    const int cnt = s_cnt;
    if (cnt == 0) return;

    // warp tiling: 2m x 4n warps, warp tile 32m x 16n
    const int m_base = (wid >> 2) * 32;
    const int n_base = (wid & 3) * 16;

    // validated ldmatrix 4-group address pattern
    const uint32_t rgrp = (uint32_t)((lane & 7) + ((lane >> 3) & 1) * 8);
    const uint32_t kofs = (uint32_t)((lane >> 4) * 8);
    const uint32_t rowA = (uint32_t)m_base + rgrp;
    const uint32_t rowB = (uint32_t)n_base + rgrp;

    float2 bc[2];
    #pragma unroll
    for (int nj = 0; nj < 2; nj++)
        bc[nj] = *(const float2*)(bias + e * PP + n_base + nj * 8 + (lane & 3) * 2);

    // A staging map: 4 threads per row, 64 floats each
    const int st_r  = tid >> 2;
    const int st_ks = (tid & 3) * 64;

    for (int m0 = 0; m0 < cnt; m0 += MT) {
        int mcount = cnt - m0;
        if (mcount > MT) mcount = MT;

        __syncthreads();   // prior tile's ldmatrix readers done

        // ---- stage A (gather + fp16 convert) ----
        if (st_r < mcount) {
            const float* xr = x + (size_t)s_rows[m0 + st_r] * DIM + st_ks;
            #pragma unroll
            for (int c = 0; c < 8; c++) {
                int kb = c * 8;
                float4 v0 = *(const float4*)(xr + kb);
                float4 v1 = *(const float4*)(xr + kb + 4);
                uint32_t so = tile_off((uint32_t)st_r, (uint32_t)(st_ks + kb));
                *(uint4*)(smem + SM_A + so) = cvt8(v0, v1);
            }
        }
        __syncthreads();

        float acc[2][2][4];
        #pragma unroll
        for (int i = 0; i < 2; i++)
            #pragma unroll
            for (int j = 0; j < 2; j++)
                #pragma unroll
                for (int q = 0; q < 4; q++) acc[i][j][q] = 0.f;

        #pragma unroll
        for (int ks = 0; ks < 16; ks++) {
            const uint32_t kk = (uint32_t)(ks * 16) + kofs;
            uint32_t aoff = tile_off(rowA, kk);
            uint32_t boff = tile_off(rowB, kk);

            uint32_t A0[4], A1[4], B[4];
            ldmx4(A0, sb + SM_A + aoff);
            ldmx4(B,  sb + SM_B + boff);
            ldmx4(A1, sb + SM_A + aoff + 16 * 512);

            // B[0],B[2] = nj0 (k0,k8); B[1],B[3] = nj1
            mma16816(acc[0][0], A0, B[0], B[2]);
            mma16816(acc[0][1], A0, B[1], B[3]);
            mma16816(acc[1][0], A1, B[0], B[2]);
            mma16816(acc[1][1], A1, B[1], B[3]);
        }

        // ---- epilogue: bias + scattered stores ----
        #pragma unroll
        for (int mi = 0; mi < 2; mi++) {
            int r0 = m_base + mi * 16 + (lane >> 2);
            int r1 = r0 + 8;
            #pragma unroll
            for (int nj = 0; nj < 2; nj++) {
                int c = n_base + nj * 8 + (lane & 3) * 2;
                if (r0 < mcount) {
                    float2 v = make_float2(acc[mi][nj][0] + bc[nj].x,
                                           acc[mi][nj][1] + bc[nj].y);
                    *(float2*)(out + (size_t)s_rows[m0 + r0] * PP + c) = v;
                }
                if (r1 < mcount) {
                    float2 v = make_float2(acc[mi][nj][2] + bc[nj].x,
                                           acc[mi][nj][3] + bc[nj].y);
                    *(float2*)(out + (size_t)s_rows[m0 + r1] * PP + c) = v;
                }
            }
        }
    }
}

extern "C" void kernel_launch(void* const* d_in, const int* in_sizes, int n_in,
                              void* d_out, int out_size) {
    const float* x    = (const float*)d_in[0];
    const float* W    = (const float*)d_in[1];
    const float* bias = (const float*)d_in[2];
    const int*   idx  = (const int*)d_in[3];
    float*       out  = (float*)d_out;

    const int n_tokens = in_sizes[3];

    prep_W<<<64, 256>>>(W);

    cudaFuncSetAttribute(moe_mma_kernel,
                         cudaFuncAttributeMaxDynamicSharedMemorySize, SMEM_DYN);

    dim3 grid((n_tokens + TCHUNK - 1) / TCHUNK, NEXP);
    moe_mma_kernel<<<grid, NTHREADS, SMEM_DYN>>>(x, bias, idx, out, n_tokens);
}

// round 13
// speedup vs baseline: 1.7256x; 1.0556x over previous
#include <cuda_runtime.h>
#include <cuda_fp16.h>
#include <cstdint>

#define NEXP     16
#define DIM      256     // K
#define PP       64      // N
#define TCHUNK   2048
#define MT       64      // M tile rows
#define NTHREADS 128

// smem (bytes): A [64][256] fp16 swizzled 32KB | B [64][256] fp16 swizzled 32KB | rows 8KB
#define SM_A     0
#define SM_B     32768
#define SM_ROWS  65536
#define SMEM_DYN 73728

// prepped weights: [E][N][K] fp16 (rounded)
__device__ __half g_Wt[NEXP * PP * DIM];

__device__ __forceinline__ uint32_t smem_u32(const void* p) {
    uint32_t a;
    asm("{ .reg .u64 t; cvta.to.shared.u64 t, %1; cvt.u32.u64 %0, t; }" : "=r"(a) : "l"(p));
    return a;
}

// Swizzled tile: row-major [r][k] fp16, row stride 512B; 16B chunks XOR-permuted
// within each 128B group -> ldmatrix (8 rows, same k-chunk) conflict-free.
__device__ __forceinline__ uint32_t tile_off(uint32_t r, uint32_t k) {
    uint32_t ch  = k >> 3;
    uint32_t chs = (ch & 24u) | ((ch ^ r) & 7u);
    return r * 512u + chs * 16u + (k & 7u) * 2u;
}

__device__ __forceinline__ void ldmx4(uint32_t (&r)[4], uint32_t a) {
    asm volatile("ldmatrix.sync.aligned.m8n8.x4.shared.b16 {%0,%1,%2,%3}, [%4];"
                 : "=r"(r[0]), "=r"(r[1]), "=r"(r[2]), "=r"(r[3]) : "r"(a));
}

__device__ __forceinline__ void mma16816(float (&d)[4], const uint32_t (&a)[4],
                                         uint32_t b0, uint32_t b1) {
    asm volatile("mma.sync.aligned.m16n8k16.row.col.f32.f16.f16.f32 "
                 "{%0,%1,%2,%3}, {%4,%5,%6,%7}, {%8,%9}, {%0,%1,%2,%3};"
                 : "+f"(d[0]), "+f"(d[1]), "+f"(d[2]), "+f"(d[3])
                 : "r"(a[0]), "r"(a[1]), "r"(a[2]), "r"(a[3]), "r"(b0), "r"(b1));
}

__device__ __forceinline__ uint32_t f16x2(float e1, float e0) {
    uint32_t r;
    asm("cvt.rn.f16x2.f32 %0, %1, %2;" : "=r"(r) : "f"(e1), "f"(e0));
    return r;
}

__device__ __forceinline__ uint4 cvt8(const float4 v0, const float4 v1) {
    uint4 o;
    o.x = f16x2(v0.y, v0.x);
    o.y = f16x2(v0.w, v0.z);
    o.z = f16x2(v1.y, v1.x);
    o.w = f16x2(v1.w, v1.z);
    return o;
}

// ---- prep: W [E][K][N] f32 -> g_Wt [E][N][K] fp16 (smem-tiled transpose) ----
__global__ void prep_W(const float* __restrict__ W) {
    __shared__ float tile[64][65];
    const int b  = blockIdx.x;          // 64 blocks: e (16) x k-seg (4)
    const int e  = b >> 2;
    const int k0 = (b & 3) * 64;
    const int t  = threadIdx.x;
    #pragma unroll
    for (int i = 0; i < 16; i++) {
        int idx = i * 256 + t;
        int kk = idx >> 6, nn = idx & 63;
        tile[kk][nn] = W[((size_t)e * DIM + k0 + kk) * PP + nn];
    }
    __syncthreads();
    #pragma unroll
    for (int i = 0; i < 16; i++) {
        int idx = i * 256 + t;
        int nn = idx >> 6, kk = idx & 63;
        g_Wt[((size_t)e * PP + nn) * DIM + k0 + kk] = __float2half_rn(tile[kk][nn]);
    }
}

extern __shared__ char smem_raw[];

__global__ __launch_bounds__(NTHREADS, 3)
void moe_mma_kernel(const float* __restrict__ x,
                    const float* __restrict__ bias,
                    const int*   __restrict__ bidx,
                    float*       __restrict__ out,
                    int n_tokens)
{
    __shared__ int s_cnt;
    char* smem = smem_raw;
    const uint32_t sb = smem_u32(smem);
    int* s_rows = (int*)(smem + SM_ROWS);

    const int tid  = threadIdx.x;
    const int wid  = tid >> 5;
    const int lane = tid & 31;
    const int e    = blockIdx.y;
    const int base = blockIdx.x * TCHUNK;

    if (tid == 0) s_cnt = 0;
    __syncthreads();

    // ---- stage B = W[e] fp16 into swizzled smem ----
    {
        const __half* wt = g_Wt + (size_t)e * PP * DIM;
        #pragma unroll 4
        for (int p = 0; p < (PP * DIM / 8) / NTHREADS; p++) {   // 16 passes
            int i  = p * NTHREADS + tid;
            int n  = i >> 5;
            int k8 = (i & 31) * 8;
            uint32_t so = tile_off((uint32_t)n, (uint32_t)k8);
            *(uint4*)(smem + SM_B + so) = *(const uint4*)(wt + (size_t)n * DIM + k8);
        }
    }

    // ---- select tokens for expert e ----
    int lim = n_tokens - base;
    if (lim > TCHUNK) lim = TCHUNK;
    for (int i = tid; i < lim; i += NTHREADS) {
        if (bidx[base + i] == e) {
            int pos = atomicAdd(&s_cnt, 1);
            s_rows[pos] = base + i;
        }
    }
    __syncthreads();
    const int cnt = s_cnt;
    if (cnt == 0) return;

    // warp tiling: 2m x 2n warps, warp tile 32m x 32n
    const int m_base = (wid >> 1) * 32;
    const int n_base = (wid & 1) * 32;

    // validated ldmatrix 4-group address pattern
    const uint32_t rgrp = (uint32_t)((lane & 7) + ((lane >> 3) & 1) * 8);
    const uint32_t kofs = (uint32_t)((lane >> 4) * 8);
    const uint32_t rowA = (uint32_t)m_base + rgrp;
    const uint32_t rowB = (uint32_t)n_base + rgrp;

    float2 bc[4];
    #pragma unroll
    for (int nj = 0; nj < 4; nj++)
        bc[nj] = *(const float2*)(bias + e * PP + n_base + nj * 8 + (lane & 3) * 2);

    // A staging map: 2 threads per row, 128 floats each
    const int st_r  = tid >> 1;
    const int st_ks = (tid & 1) * 128;

    for (int m0 = 0; m0 < cnt; m0 += MT) {
        int mcount = cnt - m0;
        if (mcount > MT) mcount = MT;

        __syncthreads();   // prior tile's ldmatrix readers done

        // ---- stage A (gather + fp16 convert) ----
        if (st_r < mcount) {
            const float* xr = x + (size_t)s_rows[m0 + st_r] * DIM + st_ks;
            #pragma unroll 4
            for (int c = 0; c < 16; c++) {
                int kb = c * 8;
                float4 v0 = *(const float4*)(xr + kb);
                float4 v1 = *(const float4*)(xr + kb + 4);
                uint32_t so = tile_off((uint32_t)st_r, (uint32_t)(st_ks + kb));
                *(uint4*)(smem + SM_A + so) = cvt8(v0, v1);
            }
        }
        __syncthreads();

        float acc[2][4][4];
        #pragma unroll
        for (int i = 0; i < 2; i++)
            #pragma unroll
            for (int j = 0; j < 4; j++)
                #pragma unroll
                for (int q = 0; q < 4; q++) acc[i][j][q] = 0.f;

        #pragma unroll
        for (int ks = 0; ks < 16; ks++) {
            const uint32_t kk = (uint32_t)(ks * 16) + kofs;
            uint32_t aoff = tile_off(rowA, kk);
            uint32_t boff = tile_off(rowB, kk);

            uint32_t A0[4], A1[4], B0[4], B1[4];
            ldmx4(A0, sb + SM_A + aoff);
            ldmx4(B0, sb + SM_B + boff);
            ldmx4(A1, sb + SM_A + aoff + 16 * 512);
            ldmx4(B1, sb + SM_B + boff + 16 * 512);

            // B0: nj0 = (B0[0],B0[2]), nj1 = (B0[1],B0[3]); B1: nj2, nj3
            mma16816(acc[0][0], A0, B0[0], B0[2]);
            mma16816(acc[0][1], A0, B0[1], B0[3]);
            mma16816(acc[0][2], A0, B1[0], B1[2]);
            mma16816(acc[0][3], A0, B1[1], B1[3]);
            mma16816(acc[1][0], A1, B0[0], B0[2]);
            mma16816(acc[1][1], A1, B0[1], B0[3]);
            mma16816(acc[1][2], A1, B1[0], B1[2]);
            mma16816(acc[1][3], A1, B1[1], B1[3]);
        }

        // ---- epilogue: bias + scattered stores ----
        #pragma unroll
        for (int mi = 0; mi < 2; mi++) {
            int r0 = m_base + mi * 16 + (lane >> 2);
            int r1 = r0 + 8;
            #pragma unroll
            for (int nj = 0; nj < 4; nj++) {
                int c = n_base + nj * 8 + (lane & 3) * 2;
                if (r0 < mcount) {
                    float2 v = make_float2(acc[mi][nj][0] + bc[nj].x,
                                           acc[mi][nj][1] + bc[nj].y);
                    *(float2*)(out + (size_t)s_rows[m0 + r0] * PP + c) = v;
                }
                if (r1 < mcount) {
                    float2 v = make_float2(acc[mi][nj][2] + bc[nj].x,
                                           acc[mi][nj][3] + bc[nj].y);
                    *(float2*)(out + (size_t)s_rows[m0 + r1] * PP + c) = v;
                }
            }
        }
    }
}

extern "C" void kernel_launch(void* const* d_in, const int* in_sizes, int n_in,
                              void* d_out, int out_size) {
    const float* x    = (const float*)d_in[0];
    const float* W    = (const float*)d_in[1];
    const float* bias = (const float*)d_in[2];
    const int*   idx  = (const int*)d_in[3];
    float*       out  = (float*)d_out;

    const int n_tokens = in_sizes[3];

    prep_W<<<64, 256>>>(W);

    cudaFuncSetAttribute(moe_mma_kernel,
                         cudaFuncAttributeMaxDynamicSharedMemorySize, SMEM_DYN);

    dim3 grid((n_tokens + TCHUNK - 1) / TCHUNK, NEXP);
    moe_mma_kernel<<<grid, NTHREADS, SMEM_DYN>>>(x, bias, idx, out, n_tokens);
}

// round 16
// speedup vs baseline: 1.7707x; 1.0261x over previous
#include <cuda_runtime.h>
#include <cuda_fp16.h>
#include <cstdint>

#define NEXP     16
#define DIM      256     // K
#define PP       64      // N
#define TCHUNK   4096
#define MT       64      // M tile rows
#define NTHREADS 128

// smem (bytes): A [64][256] fp16 swizzled 32KB | rows 16KB
#define SM_A     0
#define SM_ROWS  32768
#define SMEM_DYN 49152

// Fragment-packed weights: [e][ks 0..15][pair 0..3][lane 0..31] uint4.
// For n-pair p (covers n = p*16 .. p*16+15), lane l:
//   .x = {B[k0][n_e], B[k0+1][n_e]}   (b0 of even n-block, n_e = p*16 + l/4)
//   .y = {B[k0+8][n_e], B[k0+9][n_e]} (b1 of even n-block)
//   .z/.w = same for odd n-block (n_o = p*16 + 8 + l/4)
// with k0 = ks*16 + (l%4)*2.  (fp16; matches mma b-frag layout validated in R13)
__device__ uint4 g_Bf[NEXP * 16 * 4 * 32];   // 512 KB

__device__ __forceinline__ uint32_t smem_u32(const void* p) {
    uint32_t a;
    asm("{ .reg .u64 t; cvta.to.shared.u64 t, %1; cvt.u32.u64 %0, t; }" : "=r"(a) : "l"(p));
    return a;
}

// Swizzled A tile: row-major [r][k] fp16, row stride 512B; 16B chunks XOR-permuted
// within each 128B group -> ldmatrix (8 rows, same k-chunk) conflict-free.
__device__ __forceinline__ uint32_t tile_off(uint32_t r, uint32_t k) {
    uint32_t ch  = k >> 3;
    uint32_t chs = (ch & 24u) | ((ch ^ r) & 7u);
    return r * 512u + chs * 16u + (k & 7u) * 2u;
}

__device__ __forceinline__ void ldmx4(uint32_t (&r)[4], uint32_t a) {
    asm volatile("ldmatrix.sync.aligned.m8n8.x4.shared.b16 {%0,%1,%2,%3}, [%4];"
                 : "=r"(r[0]), "=r"(r[1]), "=r"(r[2]), "=r"(r[3]) : "r"(a));
}

__device__ __forceinline__ void mma16816(float (&d)[4], const uint32_t (&a)[4],
                                         uint32_t b0, uint32_t b1) {
    asm volatile("mma.sync.aligned.m16n8k16.row.col.f32.f16.f16.f32 "
                 "{%0,%1,%2,%3}, {%4,%5,%6,%7}, {%8,%9}, {%0,%1,%2,%3};"
                 : "+f"(d[0]), "+f"(d[1]), "+f"(d[2]), "+f"(d[3])
                 : "r"(a[0]), "r"(a[1]), "r"(a[2]), "r"(a[3]), "r"(b0), "r"(b1));
}

__device__ __forceinline__ uint32_t f16x2(float e1, float e0) {
    uint32_t r;
    asm("cvt.rn.f16x2.f32 %0, %1, %2;" : "=r"(r) : "f"(e1), "f"(e0));
    return r;
}

__device__ __forceinline__ uint4 cvt8(const float4 v0, const float4 v1) {
    uint4 o;
    o.x = f16x2(v0.y, v0.x);
    o.y = f16x2(v0.w, v0.z);
    o.z = f16x2(v1.y, v1.x);
    o.w = f16x2(v1.w, v1.z);
    return o;
}

// ---- prep: W [E][K][N] f32 -> g_Bf fragment-packed fp16 ----
__global__ void prep_Bf(const float* __restrict__ W) {
    int idx  = blockIdx.x * blockDim.x + threadIdx.x;   // 32768 threads
    if (idx >= NEXP * 16 * 4 * 32) return;
    int lane = idx & 31;
    int pair = (idx >> 5) & 3;
    int ks   = (idx >> 7) & 15;
    int e    = idx >> 11;
    int n0 = pair * 16 + (lane >> 2);
    int n1 = n0 + 8;
    int k0 = ks * 16 + (lane & 3) * 2;
    const float* w = W + (size_t)e * DIM * PP;
    uint4 v;
    v.x = f16x2(w[(k0 + 1) * PP + n0], w[(k0    ) * PP + n0]);
    v.y = f16x2(w[(k0 + 9) * PP + n0], w[(k0 + 8) * PP + n0]);
    v.z = f16x2(w[(k0 + 1) * PP + n1], w[(k0    ) * PP + n1]);
    v.w = f16x2(w[(k0 + 9) * PP + n1], w[(k0 + 8) * PP + n1]);
    g_Bf[idx] = v;
}

extern __shared__ char smem_raw[];

__global__ __launch_bounds__(NTHREADS, 4)
void moe_mma_kernel(const float* __restrict__ x,
                    const float* __restrict__ bias,
                    const int*   __restrict__ bidx,
                    float*       __restrict__ out,
                    int n_tokens)
{
    __shared__ int s_cnt;
    char* smem = smem_raw;
    const uint32_t sb = smem_u32(smem);
    int* s_rows = (int*)(smem + SM_ROWS);

    const int tid  = threadIdx.x;
    const int wid  = tid >> 5;
    const int lane = tid & 31;
    const int e    = blockIdx.y;
    const int base = blockIdx.x * TCHUNK;

    if (tid == 0) s_cnt = 0;
    __syncthreads();

    // ---- select tokens for expert e ----
    int lim = n_tokens - base;
    if (lim > TCHUNK) lim = TCHUNK;
    for (int i = tid; i < lim; i += NTHREADS) {
        if (bidx[base + i] == e) {
            int pos = atomicAdd(&s_cnt, 1);
            s_rows[pos] = base + i;
        }
    }
    __syncthreads();
    const int cnt = s_cnt;
    if (cnt == 0) return;

    // warp tiling: 2m x 2n warps, warp tile 32m x 32n
    const int m_base = (wid >> 1) * 32;
    const int n_base = (wid & 1) * 32;

    // validated ldmatrix 4-group address pattern (A only)
    const uint32_t rgrp = (uint32_t)((lane & 7) + ((lane >> 3) & 1) * 8);
    const uint32_t kofs = (uint32_t)((lane >> 4) * 8);
    const uint32_t rowA = (uint32_t)m_base + rgrp;

    // B fragment pointers: this warp's two n-pairs; stride per ks = 4*32 uint4
    const uint4* Bf = g_Bf + (((size_t)e * 16 * 4) + (size_t)(wid & 1) * 2) * 32 + lane;

    float2 bc[4];
    #pragma unroll
    for (int nj = 0; nj < 4; nj++)
        bc[nj] = *(const float2*)(bias + e * PP + n_base + nj * 8 + (lane & 3) * 2);

    // A staging map: 2 threads per row, 128 floats each
    const int st_r  = tid >> 1;
    const int st_ks = (tid & 1) * 128;

    for (int m0 = 0; m0 < cnt; m0 += MT) {
        int mcount = cnt - m0;
        if (mcount > MT) mcount = MT;

        __syncthreads();   // prior tile's ldmatrix readers done

        // ---- stage A (gather + fp16 convert) ----
        if (st_r < mcount) {
            const float* xr = x + (size_t)s_rows[m0 + st_r] * DIM + st_ks;
            #pragma unroll 4
            for (int c = 0; c < 16; c++) {
                int kb = c * 8;
                float4 v0 = *(const float4*)(xr + kb);
                float4 v1 = *(const float4*)(xr + kb + 4);
                uint32_t so = tile_off((uint32_t)st_r, (uint32_t)(st_ks + kb));
                *(uint4*)(smem + SM_A + so) = cvt8(v0, v1);
            }
        }

        // B frag prologue for ks=0 (independent of smem barrier)
        uint4 f0 = Bf[0];
        uint4 f1 = Bf[32];
        __syncthreads();

        float acc[2][4][4];
        #pragma unroll
        for (int i = 0; i < 2; i++)
            #pragma unroll
            for (int j = 0; j < 4; j++)
                #pragma unroll
                for (int q = 0; q < 4; q++) acc[i][j][q] = 0.f;

        #pragma unroll
        for (int ks = 0; ks < 16; ks++) {
            // prefetch next k-step's frags (index clamped; dead on last iter)
            const int pks = (ks < 15) ? (ks + 1) : 15;
            uint4 nf0 = Bf[pks * 128];
            uint4 nf1 = Bf[pks * 128 + 32];

            const uint32_t kk = (uint32_t)(ks * 16) + kofs;
            uint32_t aoff = tile_off(rowA, kk);
            uint32_t A0[4], A1[4];
            ldmx4(A0, sb + SM_A + aoff);
            ldmx4(A1, sb + SM_A + aoff + 16 * 512);

            // f0: nj0 = (x,y), nj1 = (z,w); f1: nj2, nj3
            mma16816(acc[0][0], A0, f0.x, f0.y);
            mma16816(acc[0][1], A0, f0.z, f0.w);
            mma16816(acc[0][2], A0, f1.x, f1.y);
            mma16816(acc[0][3], A0, f1.z, f1.w);
            mma16816(acc[1][0], A1, f0.x, f0.y);
            mma16816(acc[1][1], A1, f0.z, f0.w);
            mma16816(acc[1][2], A1, f1.x, f1.y);
            mma16816(acc[1][3], A1, f1.z, f1.w);

            f0 = nf0; f1 = nf1;
        }

        // ---- epilogue: bias + scattered stores ----
        #pragma unroll
        for (int mi = 0; mi < 2; mi++) {
            int r0 = m_base + mi * 16 + (lane >> 2);
            int r1 = r0 + 8;
            #pragma unroll
            for (int nj = 0; nj < 4; nj++) {
                int c = n_base + nj * 8 + (lane & 3) * 2;
                if (r0 < mcount) {
                    float2 v = make_float2(acc[mi][nj][0] + bc[nj].x,
                                           acc[mi][nj][1] + bc[nj].y);
                    *(float2*)(out + (size_t)s_rows[m0 + r0] * PP + c) = v;
                }
                if (r1 < mcount) {
                    float2 v = make_float2(acc[mi][nj][2] + bc[nj].x,
                                           acc[mi][nj][3] + bc[nj].y);
                    *(float2*)(out + (size_t)s_rows[m0 + r1] * PP + c) = v;
                }
            }
        }
    }
}

extern "C" void kernel_launch(void* const* d_in, const int* in_sizes, int n_in,
                              void* d_out, int out_size) {
    const float* x    = (const float*)d_in[0];
    const float* W    = (const float*)d_in[1];
    const float* bias = (const float*)d_in[2];
    const int*   idx  = (const int*)d_in[3];
    float*       out  = (float*)d_out;

    const int n_tokens = in_sizes[3];

    prep_Bf<<<(NEXP * 16 * 4 * 32 + 255) / 256, 256>>>(W);

    cudaFuncSetAttribute(moe_mma_kernel,
                         cudaFuncAttributeMaxDynamicSharedMemorySize, SMEM_DYN);

    dim3 grid((n_tokens + TCHUNK - 1) / TCHUNK, NEXP);
    moe_mma_kernel<<<grid, NTHREADS, SMEM_DYN>>>(x, bias, idx, out, n_tokens);
}

// round 17
// speedup vs baseline: 2.0005x; 1.1298x over previous
#include <cuda_runtime.h>
#include <cuda_fp16.h>
#include <cstdint>

#define NEXP     16
#define DIM      256     // K
#define PP       64      // N
#define MT       64      // M tile rows
#define NTHREADS 128
#define NTOK_MAX 262144
#define MAXTILES ((NTOK_MAX / MT) + NEXP)   // 4112

// smem (bytes): A [64][256] fp16 swizzled
#define SM_A     0
#define SMEM_DYN 32768

// Fragment-packed weights: [e][ks][pair][lane] uint4 (fp16 mma b-frags, validated R13/R16)
__device__ uint4 g_Bf[NEXP * 16 * 4 * 32];   // 512 KB

// sort scratch
__device__ int g_cnt[NEXP];
__device__ int g_cursor[NEXP];
__device__ int g_seg[NEXP];
__device__ int g_sorted[NTOK_MAX + NEXP * (MT - 1) + MT];
__device__ int g_tile_e[MAXTILES];
__device__ int g_tile_row[MAXTILES];
__device__ int g_tile_cnt[MAXTILES];

__device__ __forceinline__ uint32_t smem_u32(const void* p) {
    uint32_t a;
    asm("{ .reg .u64 t; cvta.to.shared.u64 t, %1; cvt.u32.u64 %0, t; }" : "=r"(a) : "l"(p));
    return a;
}
__device__ __forceinline__ uint32_t tile_off(uint32_t r, uint32_t k) {
    uint32_t ch  = k >> 3;
    uint32_t chs = (ch & 24u) | ((ch ^ r) & 7u);
    return r * 512u + chs * 16u + (k & 7u) * 2u;
}
__device__ __forceinline__ void ldmx4(uint32_t (&r)[4], uint32_t a) {
    asm volatile("ldmatrix.sync.aligned.m8n8.x4.shared.b16 {%0,%1,%2,%3}, [%4];"
                 : "=r"(r[0]), "=r"(r[1]), "=r"(r[2]), "=r"(r[3]) : "r"(a));
}
__device__ __forceinline__ void mma16816(float (&d)[4], const uint32_t (&a)[4],
                                         uint32_t b0, uint32_t b1) {
    asm volatile("mma.sync.aligned.m16n8k16.row.col.f32.f16.f16.f32 "
                 "{%0,%1,%2,%3}, {%4,%5,%6,%7}, {%8,%9}, {%0,%1,%2,%3};"
                 : "+f"(d[0]), "+f"(d[1]), "+f"(d[2]), "+f"(d[3])
                 : "r"(a[0]), "r"(a[1]), "r"(a[2]), "r"(a[3]), "r"(b0), "r"(b1));
}
__device__ __forceinline__ uint32_t f16x2(float e1, float e0) {
    uint32_t r;
    asm("cvt.rn.f16x2.f32 %0, %1, %2;" : "=r"(r) : "f"(e1), "f"(e0));
    return r;
}
__device__ __forceinline__ uint4 cvt8(const float4 v0, const float4 v1) {
    uint4 o;
    o.x = f16x2(v0.y, v0.x);
    o.y = f16x2(v0.w, v0.z);
    o.z = f16x2(v1.y, v1.x);
    o.w = f16x2(v1.w, v1.z);
    return o;
}

// ---- prep: W -> fragment-packed fp16 ----
__global__ void prep_Bf(const float* __restrict__ W) {
    int idx  = blockIdx.x * blockDim.x + threadIdx.x;
    if (idx >= NEXP * 16 * 4 * 32) return;
    int lane = idx & 31;
    int pair = (idx >> 5) & 3;
    int ks   = (idx >> 7) & 15;
    int e    = idx >> 11;
    int n0 = pair * 16 + (lane >> 2);
    int n1 = n0 + 8;
    int k0 = ks * 16 + (lane & 3) * 2;
    const float* w = W + (size_t)e * DIM * PP;
    uint4 v;
    v.x = f16x2(w[(k0 + 1) * PP + n0], w[(k0    ) * PP + n0]);
    v.y = f16x2(w[(k0 + 9) * PP + n0], w[(k0 + 8) * PP + n0]);
    v.z = f16x2(w[(k0 + 1) * PP + n1], w[(k0    ) * PP + n1]);
    v.w = f16x2(w[(k0 + 9) * PP + n1], w[(k0 + 8) * PP + n1]);
    g_Bf[idx] = v;
}

// ---- sort k1: histogram (g_cnt must be zero on entry; k_meta re-zeros it) ----
__global__ void k_hist(const int* __restrict__ bidx, int n) {
    __shared__ int h[NEXP];
    if (threadIdx.x < NEXP) h[threadIdx.x] = 0;
    __syncthreads();
    int i = blockIdx.x * blockDim.x + threadIdx.x;
    int stride = gridDim.x * blockDim.x;
    for (; i < n; i += stride) atomicAdd(&h[bidx[i]], 1);
    __syncthreads();
    if (threadIdx.x < NEXP) atomicAdd(&g_cnt[threadIdx.x], h[threadIdx.x]);
}

// ---- sort k2: padded segments + tile metadata (single block) ----
__global__ void k_meta() {
    __shared__ int scnt[NEXP], srow[NEXP], stile[NEXP];
    const int t = threadIdx.x;
    if (t == 0) {
        int row = 0, tile = 0;
        for (int e = 0; e < NEXP; e++) {
            int c = g_cnt[e];
            scnt[e] = c; srow[e] = row; stile[e] = tile;
            g_seg[e] = row;
            g_cursor[e] = 0;
            g_cnt[e] = 0;                 // self-clean for next replay
            int nt = (c + MT - 1) / MT;
            row += nt * MT;
            tile += nt;
        }
    }
    __syncthreads();
    for (int i = t; i < MAXTILES; i += blockDim.x) g_tile_cnt[i] = 0;
    __syncthreads();
    for (int e = 0; e < NEXP; e++) {
        int c  = scnt[e];
        int nt = (c + MT - 1) / MT;
        for (int i = t; i < nt; i += blockDim.x) {
            int tl = stile[e] + i;
            g_tile_e[tl]   = e;
            g_tile_row[tl] = srow[e] + i * MT;
            int rem = c - i * MT;
            g_tile_cnt[tl] = rem < MT ? rem : MT;
        }
    }
}

// ---- sort k3: block-aggregated multisplit scatter (order irrelevant) ----
__global__ void k_scatter(const int* __restrict__ bidx, int n) {
    __shared__ int wcnt[16][NEXP];    // [warp][expert]
    __shared__ int woff[16][NEXP];
    __shared__ int bbase[NEXP];
    const int tid  = threadIdx.x;     // 512 threads = 16 warps
    const int wid  = tid >> 5;
    const int lane = tid & 31;
    const int i    = blockIdx.x * 512 + tid;

    if (tid < 16 * NEXP) ((int*)wcnt)[tid] = 0;
    __syncthreads();

    int e = (i < n) ? bidx[i] : NEXP;            // NEXP = dummy bucket
    unsigned mask = __match_any_sync(0xFFFFFFFFu, e);
    int rank   = __popc(mask & ((1u << lane) - 1));
    int leader = __ffs(mask) - 1;
    if (lane == leader && e < NEXP) wcnt[wid][e] = __popc(mask);
    __syncthreads();

    if (tid < NEXP) {
        int s = 0;
        #pragma unroll
        for (int w = 0; w < 16; w++) { woff[w][tid] = s; s += wcnt[w][tid]; }
        bbase[tid] = s ? atomicAdd(&g_cursor[tid], s) : 0;
    }
    __syncthreads();

    if (e < NEXP)
        g_sorted[g_seg[e] + bbase[e] + woff[wid][e] + rank] = i;
}

extern __shared__ char smem_raw[];

// ---- main GEMM: one full 64-row tile per CTA ----
__global__ __launch_bounds__(NTHREADS, 5)
void moe_mma_kernel(const float* __restrict__ x,
                    const float* __restrict__ bias,
                    float*       __restrict__ out)
{
    const int t = blockIdx.x;
    const int mcount = g_tile_cnt[t];
    if (mcount == 0) return;
    const int e    = g_tile_e[t];
    const int* rows = g_sorted + g_tile_row[t];

    char* smem = smem_raw;
    const uint32_t sb = smem_u32(smem);

    const int tid  = threadIdx.x;
    const int wid  = tid >> 5;
    const int lane = tid & 31;

    // warp tiling: 2m x 2n warps, warp tile 32m x 32n
    const int m_base = (wid >> 1) * 32;
    const int n_base = (wid & 1) * 32;

    const uint32_t rgrp = (uint32_t)((lane & 7) + ((lane >> 3) & 1) * 8);
    const uint32_t kofs = (uint32_t)((lane >> 4) * 8);
    const uint32_t rowA = (uint32_t)m_base + rgrp;

    const uint4* Bf = g_Bf + (((size_t)e * 16 * 4) + (size_t)(wid & 1) * 2) * 32 + lane;

    float2 bc[4];
    #pragma unroll
    for (int nj = 0; nj < 4; nj++)
        bc[nj] = *(const float2*)(bias + e * PP + n_base + nj * 8 + (lane & 3) * 2);

    // A staging: 2 threads per row, 128 floats each
    const int st_r  = tid >> 1;
    const int st_ks = (tid & 1) * 128;

    if (st_r < mcount) {
        const float* xr = x + (size_t)rows[st_r] * DIM + st_ks;
        #pragma unroll 4
        for (int c = 0; c < 16; c++) {
            int kb = c * 8;
            float4 v0 = *(const float4*)(xr + kb);
            float4 v1 = *(const float4*)(xr + kb + 4);
            uint32_t so = tile_off((uint32_t)st_r, (uint32_t)(st_ks + kb));
            *(uint4*)(smem + SM_A + so) = cvt8(v0, v1);
        }
    }

    // B frag prologue (independent of smem barrier)
    uint4 f0 = Bf[0];
    uint4 f1 = Bf[32];
    __syncthreads();

    float acc[2][4][4];
    #pragma unroll
    for (int i = 0; i < 2; i++)
        #pragma unroll
        for (int j = 0; j < 4; j++)
            #pragma unroll
            for (int q = 0; q < 4; q++) acc[i][j][q] = 0.f;

    #pragma unroll
    for (int ks = 0; ks < 16; ks++) {
        const int pks = (ks < 15) ? (ks + 1) : 15;
        uint4 nf0 = Bf[pks * 128];
        uint4 nf1 = Bf[pks * 128 + 32];

        const uint32_t kk = (uint32_t)(ks * 16) + kofs;
        uint32_t aoff = tile_off(rowA, kk);
        uint32_t A0[4], A1[4];
        ldmx4(A0, sb + SM_A + aoff);
        ldmx4(A1, sb + SM_A + aoff + 16 * 512);

        mma16816(acc[0][0], A0, f0.x, f0.y);
        mma16816(acc[0][1], A0, f0.z, f0.w);
        mma16816(acc[0][2], A0, f1.x, f1.y);
        mma16816(acc[0][3], A0, f1.z, f1.w);
        mma16816(acc[1][0], A1, f0.x, f0.y);
        mma16816(acc[1][1], A1, f0.z, f0.w);
        mma16816(acc[1][2], A1, f1.x, f1.y);
        mma16816(acc[1][3], A1, f1.z, f1.w);

        f0 = nf0; f1 = nf1;
    }

    // epilogue: bias + scattered stores
    #pragma unroll
    for (int mi = 0; mi < 2; mi++) {
        int r0 = m_base + mi * 16 + (lane >> 2);
        int r1 = r0 + 8;
        #pragma unroll
        for (int nj = 0; nj < 4; nj++) {
            int c = n_base + nj * 8 + (lane & 3) * 2;
            if (r0 < mcount) {
                float2 v = make_float2(acc[mi][nj][0] + bc[nj].x,
                                       acc[mi][nj][1] + bc[nj].y);
                *(float2*)(out + (size_t)rows[r0] * PP + c) = v;
            }
            if (r1 < mcount) {
                float2 v = make_float2(acc[mi][nj][2] + bc[nj].x,
                                       acc[mi][nj][3] + bc[nj].y);
                *(float2*)(out + (size_t)rows[r1] * PP + c) = v;
            }
        }
    }
}

extern "C" void kernel_launch(void* const* d_in, const int* in_sizes, int n_in,
                              void* d_out, int out_size) {
    const float* x    = (const float*)d_in[0];
    const float* W    = (const float*)d_in[1];
    const float* bias = (const float*)d_in[2];
    const int*   idx  = (const int*)d_in[3];
    float*       out  = (float*)d_out;

    const int n_tokens = in_sizes[3];

    prep_Bf<<<(NEXP * 16 * 4 * 32 + 255) / 256, 256>>>(W);
    k_hist<<<256, 256>>>(idx, n_tokens);
    k_meta<<<1, 256>>>();
    k_scatter<<<(n_tokens + 511) / 512, 512>>>(idx, n_tokens);

    cudaFuncSetAttribute(moe_mma_kernel,
                         cudaFuncAttributeMaxDynamicSharedMemorySize, SMEM_DYN);

    int ntiles = n_tokens / MT + NEXP;   // upper bound; empty tiles exit early
    moe_mma_kernel<<<ntiles, NTHREADS, SMEM_DYN>>>(x, bias, out);
}